// round 15
// baseline (speedup 1.0000x reference)
#include <cuda_runtime.h>
#include <cuda_fp16.h>
#include <cstdint>
#include <math.h>

#define TOKENS   8192
#define DM       1024
#define DFF      4096
#define NE       8
#define NSLOTS   (TOKENS * 2)

#define MT_MAX   (NSLOTS / 128 + NE)   // 136 padded m-tiles max
#define PADSLOTS (MT_MAX * 128)        // 17408
#define KCH1     (DM / 32)             // 32 K32 blocks (layout unit)
#define KCH2     (DFF / 32)            // 128 K32 blocks
#define KC64_1   (DM / 64)             // 16 mainloop chunks GEMM1
#define KC64_2   (DFF / 64)            // 64 mainloop chunks GEMM2
#define NT1      (DFF / 256)           // 16 n-tiles GEMM1 (N tile = 256)
#define NT2      (DM / 256)            // 4  n-tiles GEMM2

#define STAGES   4
// per stage: A 16KB + B 32KB (K64 chunk, pure fp16)
#define STAGE_B  49152
#define SMEM_DYN (STAGES * STAGE_B + 64)

// ---------------- static device scratch (fragment-linear tiled) ----------------
__device__ __align__(16) __half g_A1[(size_t)PADSLOTS * DM];
__device__ __align__(16) __half g_B1[(size_t)NE * DFF * DM];
__device__ __align__(16) __half g_H [(size_t)PADSLOTS * DFF];
__device__ __align__(16) __half g_B2[(size_t)NE * DM * DFF];
__device__ __align__(16) float  g_P [(size_t)PADSLOTS * DM];   // gated partials (slot order)

__device__ int   g_tope[NSLOTS];
__device__ float g_topp[NSLOTS];
__device__ int   g_tok_pad[PADSLOTS];
__device__ float g_gw_pad[PADSLOTS];
__device__ int   g_inv[NSLOTS];        // token -> its two slots
__device__ int   g_count[NE];
__device__ int   g_cursor[NE];
__device__ int   g_offpad[NE];
__device__ int   g_mt_e[MT_MAX];
__device__ int   g_mt_valid[MT_MAX];
__device__ int   g_nmt;

struct alignas(16) H8 { __half h[8]; };

// ---------------- PTX helpers ----------------
__device__ __forceinline__ uint32_t smem_u32(const void* p) {
    uint32_t a;
    asm("{ .reg .u64 t; cvta.to.shared.u64 t, %1; cvt.u32.u64 %0, t; }" : "=r"(a) : "l"(p));
    return a;
}
#define MBAR_INIT(a, c) \
    asm volatile("mbarrier.init.shared.b64 [%0], %1;" :: "r"(a), "r"((uint32_t)(c)) : "memory")
#define MBAR_EXPECT_TX(a, b) \
    asm volatile("mbarrier.arrive.expect_tx.shared.b64 _, [%0], %1;" :: "r"(a), "r"((uint32_t)(b)) : "memory")
#define MBAR_ARRIVE(a) \
    asm volatile("mbarrier.arrive.shared.b64 _, [%0];" :: "r"(a) : "memory")

__device__ __forceinline__ void mbar_wait(uint32_t mbar, uint32_t parity) {
    asm volatile(
        "{\n\t.reg .pred P;\n"
        "WL_%=:\n\t"
        "mbarrier.try_wait.parity.acquire.cta.shared::cta.b64 P, [%0], %1, 0x989680;\n\t"
        "@P bra.uni WD_%=;\n\t"
        "bra.uni WL_%=;\n"
        "WD_%=:\n\t}"
        :: "r"(mbar), "r"(parity) : "memory");
}
__device__ __forceinline__ void mbar_wait_relaxed(uint32_t mbar, uint32_t parity) {
    asm volatile(
        "{\n\t.reg .pred P;\n"
        "WL_%=:\n\t"
        "mbarrier.try_wait.parity.relaxed.cta.shared::cta.b64 P, [%0], %1, 0x989680;\n\t"
        "@P bra.uni WD_%=;\n\t"
        "bra.uni WL_%=;\n"
        "WD_%=:\n\t}"
        :: "r"(mbar), "r"(parity) : "memory");
}
__device__ __forceinline__ void bulk_g2s(uint32_t dst, const void* src, uint32_t bytes, uint32_t mbar) {
    asm volatile(
        "cp.async.bulk.shared::cluster.global.mbarrier::complete_tx::bytes [%0], [%1], %2, [%3];"
        :: "r"(dst), "l"(src), "r"(bytes), "r"(mbar) : "memory");
}
__device__ __forceinline__ uint4 lds128(uint32_t a) {
    uint4 v;
    asm volatile("ld.shared.v4.u32 {%0,%1,%2,%3}, [%4];"
                 : "=r"(v.x), "=r"(v.y), "=r"(v.z), "=r"(v.w) : "r"(a));
    return v;
}
__device__ __forceinline__ void mma_f16(float* c, const uint32_t* a, uint32_t b0, uint32_t b1) {
    asm volatile(
        "mma.sync.aligned.m16n8k16.row.col.f32.f16.f16.f32 "
        "{%0,%1,%2,%3}, {%4,%5,%6,%7}, {%8,%9}, {%0,%1,%2,%3};"
        : "+f"(c[0]), "+f"(c[1]), "+f"(c[2]), "+f"(c[3])
        : "r"(a[0]), "r"(a[1]), "r"(a[2]), "r"(a[3]), "r"(b0), "r"(b1));
}
__device__ __forceinline__ uint32_t pack_h2(__half a, __half b) {
    __half2 h = __halves2half2(a, b);
    return *(uint32_t*)&h;
}

// ---------------- kernel 0: routing-state init ----------------
__global__ void init_kernel() {
    const int gid = blockIdx.x * blockDim.x + threadIdx.x;
    if (gid < PADSLOTS) g_tok_pad[gid] = -1;
    if (gid < NE) { g_count[gid] = 0; g_cursor[gid] = 0; }
}

// ---------------- kernel 1: gating (warp per token, float4 loads) ----------------
__global__ void __launch_bounds__(256) gate_kernel(
    const float* __restrict__ x, const float* __restrict__ gw, const float* __restrict__ gb)
{
    const int warp = (blockIdx.x * blockDim.x + threadIdx.x) >> 5;
    const int lane = threadIdx.x & 31;
    if (warp >= TOKENS) return;

    // each lane loads 2 float4 per 256-element pass (DM/256 = 4 passes, MLP 8)
    const float4* xr = (const float4*)(x + (size_t)warp * DM);
    float acc[NE];
#pragma unroll
    for (int e = 0; e < NE; e++) acc[e] = 0.f;

#pragma unroll
    for (int p = 0; p < DM / 256; p++) {
        const float4 va = xr[p * 64 + lane];
        const float4 vb = xr[p * 64 + 32 + lane];
        const int d0 = p * 256 + lane * 4;
        const int d1 = p * 256 + 128 + lane * 4;
        const float av[4] = { va.x, va.y, va.z, va.w };
        const float bv[4] = { vb.x, vb.y, vb.z, vb.w };
#pragma unroll
        for (int q = 0; q < 4; q++) {
            const float4 g0 = *(const float4*)(gw + (size_t)(d0 + q) * NE);
            const float4 g1 = *(const float4*)(gw + (size_t)(d0 + q) * NE + 4);
            acc[0] += av[q] * g0.x;  acc[1] += av[q] * g0.y;
            acc[2] += av[q] * g0.z;  acc[3] += av[q] * g0.w;
            acc[4] += av[q] * g1.x;  acc[5] += av[q] * g1.y;
            acc[6] += av[q] * g1.z;  acc[7] += av[q] * g1.w;
        }
#pragma unroll
        for (int q = 0; q < 4; q++) {
            const float4 g0 = *(const float4*)(gw + (size_t)(d1 + q) * NE);
            const float4 g1 = *(const float4*)(gw + (size_t)(d1 + q) * NE + 4);
            acc[0] += bv[q] * g0.x;  acc[1] += bv[q] * g0.y;
            acc[2] += bv[q] * g0.z;  acc[3] += bv[q] * g0.w;
            acc[4] += bv[q] * g1.x;  acc[5] += bv[q] * g1.y;
            acc[6] += bv[q] * g1.z;  acc[7] += bv[q] * g1.w;
        }
    }
#pragma unroll
    for (int e = 0; e < NE; e++) {
#pragma unroll
        for (int off = 16; off; off >>= 1)
            acc[e] += __shfl_xor_sync(0xffffffffu, acc[e], off);
    }
    if (lane == 0) {
        float m = -1e30f;
#pragma unroll
        for (int e = 0; e < NE; e++) { acc[e] += gb[e]; m = fmaxf(m, acc[e]); }
        float s = 0.f;
#pragma unroll
        for (int e = 0; e < NE; e++) { acc[e] = __expf(acc[e] - m); s += acc[e]; }
        const float inv = 1.f / s;
        int i1 = 0; float p1 = acc[0];
#pragma unroll
        for (int e = 1; e < NE; e++) if (acc[e] > p1) { p1 = acc[e]; i1 = e; }
        int i2 = -1; float p2 = -1.f;
#pragma unroll
        for (int e = 0; e < NE; e++) if (e != i1 && acc[e] > p2) { p2 = acc[e]; i2 = e; }
        g_tope[2 * warp + 0] = i1;  g_topp[2 * warp + 0] = p1 * inv;
        g_tope[2 * warp + 1] = i2;  g_topp[2 * warp + 1] = p2 * inv;
        atomicAdd(&g_count[i1], 1);
        atomicAdd(&g_count[i2], 1);
    }
}

// ---------------- kernel 2: scan + padded mtile tables ----------------
__global__ void scan_kernel() {
    int o = 0, m = 0;
    for (int e = 0; e < NE; e++) {
        g_offpad[e] = o;
        const int c = g_count[e];
        const int nt = (c + 127) >> 7;
        for (int t = 0; t < nt; t++) {
            g_mt_e[m] = e;
            g_mt_valid[m] = min(128, c - t * 128);
            m++;
        }
        o += nt * 128;
    }
    g_nmt = m;
}

// ---------------- kernel 3: scatter + inverse map ----------------
__global__ void scatter_kernel() {
    const int t = blockIdx.x * blockDim.x + threadIdx.x;
    if (t >= TOKENS) return;
#pragma unroll
    for (int k = 0; k < 2; k++) {
        const int e = g_tope[2 * t + k];
        const float p = g_topp[2 * t + k];
        const int pos = g_offpad[e] + atomicAdd(&g_cursor[e], 1);
        g_tok_pad[pos] = t;
        g_gw_pad[pos] = p;
        g_inv[2 * t + k] = pos;
    }
}

// ---------------- pregather x -> fragment-linear tiled A1 (fp16) ----------------
__global__ void __launch_bounds__(256) pregather_x(const float* __restrict__ x) {
    const int mt = blockIdx.y;
    if (mt >= g_nmt) return;
    const int kc = blockIdx.x;
    const size_t blk = ((size_t)mt * KCH1 + kc) * 4096;

    for (int f = threadIdx.x; f < 512; f += 256) {
        const int lane = f & 31, w = f >> 5;
        const int ks = w & 1, mi = (w >> 1) & 3, wm = w >> 3;
        const int g = lane >> 2, t = lane & 3;
        const int k0 = kc * 32 + ks * 16 + 2 * t;
        H8 hh;
#pragma unroll
        for (int rr = 0; rr < 2; rr++) {
            const int slot = mt * 128 + wm * 64 + mi * 16 + g + rr * 8;
            const int tok = g_tok_pad[slot];
            float v0 = 0.f, v1 = 0.f, v2 = 0.f, v3 = 0.f;
            if (tok >= 0) {
                const float2 p0 = *(const float2*)(x + (size_t)tok * DM + k0);
                const float2 p1 = *(const float2*)(x + (size_t)tok * DM + k0 + 8);
                v0 = p0.x; v1 = p0.y; v2 = p1.x; v3 = p1.y;
            }
            hh.h[rr * 2 + 0] = __float2half_rn(v0);
            hh.h[rr * 2 + 1] = __float2half_rn(v1);
            hh.h[4 + rr * 2 + 0] = __float2half_rn(v2);
            hh.h[4 + rr * 2 + 1] = __float2half_rn(v3);
        }
        *(uint4*)(g_A1 + blk + (size_t)f * 8) = *(uint4*)&hh;
    }
}

// ---------------- weight tilers: [E][K][N] -> fragment-linear B blocks (N tile 256) ------
template<int N, int NT, int KCH>
__global__ void __launch_bounds__(256) tile_w(
    const float* __restrict__ w, __half* __restrict__ bdst)
{
    const int e = blockIdx.z, nt = blockIdx.y, kc = blockIdx.x;
    const size_t blk = (((size_t)e * NT + nt) * KCH + kc) * 8192;
    const float* we = w + (size_t)e * (size_t)(N) * (NT == NT1 ? DM : DFF);
    const int K_LD = N;

    for (int f = threadIdx.x; f < 1024; f += 256) {
        const int lane = f & 31, wi = f >> 5;
        const int ks = wi & 1, np = (wi >> 1) & 3, wn = wi >> 3;
        const int g = lane >> 2, t = lane & 3;
        const int kb = kc * 32 + ks * 16 + 2 * t;
        H8 hh;
#pragma unroll
        for (int sub = 0; sub < 2; sub++) {
            const int n = nt * 256 + wn * 64 + (2 * np + sub) * 8 + g;
            const int kk[4] = { kb, kb + 1, kb + 8, kb + 9 };
#pragma unroll
            for (int q = 0; q < 4; q++) {
                hh.h[sub * 4 + q] = __float2half_rn(we[(size_t)kk[q] * K_LD + n]);
            }
        }
        *(uint4*)(bdst + blk + (size_t)f * 8) = *(uint4*)&hh;
    }
}

// ---------------- pipelined fragment GEMM: CTA 128x256, warp 64x64, K64 chunks ------
template<int KCH64, int NT, int NDIM, bool IS_G1>
__global__ void __launch_bounds__(256, 1) moe_gemm(
    const __half* __restrict__ A,
    const __half* __restrict__ B,
    const float* __restrict__ bias,
    __half* __restrict__ oH,
    float* __restrict__ oP)
{
    const int mt = blockIdx.x;           // mt fastest -> in-flight CTAs share B (L2 reuse)
    if (mt >= g_nmt) return;
    const int nt = blockIdx.y;
    const int e = g_mt_e[mt];
    const int valid = g_mt_valid[mt];

    extern __shared__ __align__(128) char smem[];
    const uint32_t SB = smem_u32(smem);
    const uint32_t FULLB  = SB + STAGES * STAGE_B;
    const uint32_t EMPTYB = FULLB + 8 * STAGES;

    const int tid = threadIdx.x;
    const int warp = tid >> 5;
    const int lane = tid & 31;

    if (tid == 0) {
#pragma unroll
        for (int s = 0; s < STAGES; s++) {
            MBAR_INIT(FULLB + 8 * s, 1);
            MBAR_INIT(EMPTYB + 8 * s, 8);
        }
    }
    __syncthreads();

    const char* abase = (const char*)A + ((size_t)mt * KCH64) * 16384;
    const char* bbase = (const char*)B + (((size_t)e * NT + nt) * KCH64) * 32768;

    // prologue: fill first 3 stages (prefetch depth 3)
    if (tid == 0) {
#pragma unroll
        for (int c = 0; c < 3 && c < KCH64; c++) {
            const uint32_t sa = SB + c * STAGE_B;
            MBAR_EXPECT_TX(FULLB + 8 * c, STAGE_B);
            bulk_g2s(sa,         abase + (size_t)c * 16384, 16384, FULLB + 8 * c);
            bulk_g2s(sa + 16384, bbase + (size_t)c * 32768, 32768, FULLB + 8 * c);
        }
    }

    const int warpM = warp & 1, warpN = warp >> 1;    // 2 x 4 warp grid, 64x64 tiles
    uint32_t aoff[4][2], boff[4][2];
#pragma unroll
    for (int mi = 0; mi < 4; mi++)
#pragma unroll
        for (int ks = 0; ks < 2; ks++)
            aoff[mi][ks] = (uint32_t)((lane + 32 * (ks + 2 * mi + 8 * warpM)) * 16);
#pragma unroll
    for (int np = 0; np < 4; np++)
#pragma unroll
        for (int ks = 0; ks < 2; ks++)
            boff[np][ks] = (uint32_t)((lane + 32 * (ks + 2 * np + 8 * warpN)) * 16);

    float acc[4][8][4];
#pragma unroll
    for (int i = 0; i < 4; i++)
#pragma unroll
        for (int j = 0; j < 8; j++)
#pragma unroll
            for (int k = 0; k < 4; k++) acc[i][j][k] = 0.f;

    // producer cursor for chunk c+3: first wait on fresh EMPTY uses parity 1
    int pst = 3, pph = 1;
    int cst = 0, cph = 0;

    for (int c = 0; c < KCH64; c++) {
        mbar_wait(FULLB + 8 * cst, cph);

        // early issue: enqueue chunk c+3 loads BEFORE computing chunk c
        if (tid == 0 && c + 3 < KCH64) {
            mbar_wait_relaxed(EMPTYB + 8 * pst, pph);
            const uint32_t da = SB + pst * STAGE_B;
            MBAR_EXPECT_TX(FULLB + 8 * pst, STAGE_B);
            bulk_g2s(da,         abase + (size_t)(c + 3) * 16384, 16384, FULLB + 8 * pst);
            bulk_g2s(da + 16384, bbase + (size_t)(c + 3) * 32768, 32768, FULLB + 8 * pst);
            if (++pst == STAGES) { pst = 0; pph ^= 1; }
        }

        const uint32_t sa = SB + cst * STAGE_B;
#pragma unroll
        for (int sub = 0; sub < 2; sub++) {       // two K32 blocks per chunk
            const uint32_t saA = sa + sub * 8192;
            const uint32_t saB = sa + 16384 + sub * 16384;
#pragma unroll
            for (int ks = 0; ks < 2; ks++) {
                uint4 bh[4];
#pragma unroll
                for (int np = 0; np < 4; np++)
                    bh[np] = lds128(saB + boff[np][ks]);
#pragma unroll
                for (int mi = 0; mi < 4; mi++) {
                    const uint4 ah = lds128(saA + aoff[mi][ks]);
#pragma unroll
                    for (int np = 0; np < 4; np++) {
                        mma_f16(acc[mi][2 * np],     (const uint32_t*)&ah, bh[np].x, bh[np].y);
                        mma_f16(acc[mi][2 * np + 1], (const uint32_t*)&ah, bh[np].z, bh[np].w);
                    }
                }
            }
        }
        __syncwarp();
        if (lane == 0) MBAR_ARRIVE(EMPTYB + 8 * cst);
        if (++cst == STAGES) { cst = 0; cph ^= 1; }
    }

    // ---------------- epilogue ----------------
    const int g = lane >> 2, t = lane & 3;
    if (IS_G1) {
        // Write H in G2's A-fragment-linear layout (bias + SiLU, fp16).
#pragma unroll
        for (int n8 = 0; n8 < 8; n8++) {
            const int col = nt * 256 + warpN * 64 + n8 * 8 + 2 * t;
            const float b0 = bias[(size_t)e * NDIM + col];
            const float b1 = bias[(size_t)e * NDIM + col + 1];
            const int kcH = nt * 8 + warpN * 2 + (n8 >> 2);
            const int ks2 = (n8 >> 1) & 1;
#pragma unroll
            for (int mi = 0; mi < 4; mi++) {
                const int r0 = warpM * 64 + mi * 16 + g;
                float v0 = acc[mi][n8][0] + b0, v1 = acc[mi][n8][1] + b1;
                float v2 = acc[mi][n8][2] + b0, v3 = acc[mi][n8][3] + b1;
                v0 = v0 / (1.f + __expf(-v0));
                v1 = v1 / (1.f + __expf(-v1));
                v2 = v2 / (1.f + __expf(-v2));
                v3 = v3 / (1.f + __expf(-v3));
                if (r0 >= valid)     { v0 = 0.f; v1 = 0.f; }
                if (r0 + 8 >= valid) { v2 = 0.f; v3 = 0.f; }
                const __half h0 = __float2half_rn(v0), h1 = __float2half_rn(v1);
                const __half h2 = __float2half_rn(v2), h3 = __float2half_rn(v3);
                const int fA = lane + 32 * (ks2 + 2 * mi + 8 * warpM);
                const size_t off = ((size_t)mt * (DFF / 32) + kcH) * 4096 +
                                   (size_t)fA * 8 + (size_t)(n8 & 1) * 4;
                uint2 sh;
                sh.x = pack_h2(h0, h1);  sh.y = pack_h2(h2, h3);
                *(uint2*)(oH + off) = sh;
            }
        }
    } else {
        // gated coalesced partial stores (slot order); combined later per token
#pragma unroll
        for (int mi = 0; mi < 4; mi++) {
            const int r0 = warpM * 64 + mi * 16 + g;
            const int slot0 = mt * 128 + r0;
            const int slot1 = slot0 + 8;
            const bool ok0 = r0 < valid;
            const bool ok1 = (r0 + 8) < valid;
            const float gw0 = ok0 ? g_gw_pad[slot0] : 0.f;
            const float gw1 = ok1 ? g_gw_pad[slot1] : 0.f;
#pragma unroll
            for (int n8 = 0; n8 < 8; n8++) {
                const int col = nt * 256 + warpN * 64 + n8 * 8 + 2 * t;
                const float b0 = bias[(size_t)e * NDIM + col];
                const float b1 = bias[(size_t)e * NDIM + col + 1];
                if (ok0) {
                    float2 v = make_float2(gw0 * (acc[mi][n8][0] + b0),
                                           gw0 * (acc[mi][n8][1] + b1));
                    *(float2*)(oP + (size_t)slot0 * DM + col) = v;
                }
                if (ok1) {
                    float2 v = make_float2(gw1 * (acc[mi][n8][2] + b0),
                                           gw1 * (acc[mi][n8][3] + b1));
                    *(float2*)(oP + (size_t)slot1 * DM + col) = v;
                }
            }
        }
    }
}

// ---------------- combine: out[t] = P[slot0(t)] + P[slot1(t)] ----------------
__global__ void __launch_bounds__(256) combine_kernel(float4* __restrict__ out) {
    const int t = blockIdx.x;
    const int d = threadIdx.x;            // DM/4 = 256 float4 per token
    const int s0 = g_inv[2 * t + 0];
    const int s1 = g_inv[2 * t + 1];
    const float4 a = *(const float4*)(g_P + (size_t)s0 * DM + d * 4);
    const float4 b = *(const float4*)(g_P + (size_t)s1 * DM + d * 4);
    out[(size_t)t * (DM / 4) + d] = make_float4(a.x + b.x, a.y + b.y, a.z + b.z, a.w + b.w);
}

// ---------------- launch ----------------
extern "C" void kernel_launch(void* const* d_in, const int* in_sizes, int n_in,
                              void* d_out, int out_size)
{
    const float* x      = (const float*)d_in[0];
    const float* gate_w = (const float*)d_in[1];
    const float* gate_b = (const float*)d_in[2];
    const float* w1     = (const float*)d_in[3];
    const float* b1     = (const float*)d_in[4];
    const float* w2     = (const float*)d_in[5];
    const float* b2     = (const float*)d_in[6];
    float* out = (float*)d_out;

    cudaFuncSetAttribute(moe_gemm<KC64_1, NT1, DFF, true>,
                         cudaFuncAttributeMaxDynamicSharedMemorySize, SMEM_DYN);
    cudaFuncSetAttribute(moe_gemm<KC64_2, NT2, DM, false>,
                         cudaFuncAttributeMaxDynamicSharedMemorySize, SMEM_DYN);

    __half *a1, *b1t, *h, *b2t;
    float *pbuf;
    cudaGetSymbolAddress((void**)&a1,   g_A1);
    cudaGetSymbolAddress((void**)&b1t,  g_B1);
    cudaGetSymbolAddress((void**)&h,    g_H);
    cudaGetSymbolAddress((void**)&b2t,  g_B2);
    cudaGetSymbolAddress((void**)&pbuf, g_P);

    // forked capture branch for weight tiling (independent of x-routing chain).
    // Handles created per call and deliberately not destroyed (few calls total;
    // destroying a stream mid-capture is hazardous). No device memory allocated.
    cudaStream_t s1;
    cudaEvent_t evRoot, evW1, evW2;
    cudaStreamCreateWithFlags(&s1, cudaStreamNonBlocking);
    cudaEventCreateWithFlags(&evRoot, cudaEventDisableTiming);
    cudaEventCreateWithFlags(&evW1, cudaEventDisableTiming);
    cudaEventCreateWithFlags(&evW2, cudaEventDisableTiming);

    cudaEventRecord(evRoot, 0);
    cudaStreamWaitEvent(s1, evRoot, 0);

    // branch s1: weight tiling
    tile_w<DFF, NT1, KCH1><<<dim3(KCH1, NT1, NE), 256, 0, s1>>>(w1, b1t);
    cudaEventRecord(evW1, s1);
    tile_w<DM,  NT2, KCH2><<<dim3(KCH2, NT2, NE), 256, 0, s1>>>(w2, b2t);
    cudaEventRecord(evW2, s1);

    // main branch: routing + x prep
    init_kernel<<<PADSLOTS / 256, 256>>>();
    gate_kernel<<<TOKENS / 8, 256>>>(x, gate_w, gate_b);
    scan_kernel<<<1, 1>>>();
    scatter_kernel<<<TOKENS / 256, 256>>>();
    pregather_x<<<dim3(KCH1, MT_MAX), 256>>>(x);

    cudaStreamWaitEvent(0, evW1, 0);
    moe_gemm<KC64_1, NT1, DFF, true><<<dim3(MT_MAX, NT1), 256, SMEM_DYN>>>(
        a1, b1t, b1, h, nullptr);

    cudaStreamWaitEvent(0, evW2, 0);
    moe_gemm<KC64_2, NT2, DM, false><<<dim3(MT_MAX, NT2), 256, SMEM_DYN>>>(
        h, b2t, b2, nullptr, pbuf);

    combine_kernel<<<TOKENS, 256>>>((float4*)out);
}

// round 16
// speedup vs baseline: 1.0366x; 1.0366x over previous
#include <cuda_runtime.h>
#include <cuda_fp16.h>
#include <cstdint>
#include <math.h>

#define TOKENS   8192
#define DM       1024
#define DFF      4096
#define NE       8
#define NSLOTS   (TOKENS * 2)

#define MT_MAX   (NSLOTS / 128 + NE)   // 136 padded m-tiles max
#define PADSLOTS (MT_MAX * 128)        // 17408
#define KCH1     (DM / 32)             // 32 K32 blocks (layout unit)
#define KCH2     (DFF / 32)            // 128 K32 blocks
#define KC64_1   (DM / 64)             // 16 mainloop chunks GEMM1
#define KC64_2   (DFF / 64)            // 64 mainloop chunks GEMM2
#define NT1      (DFF / 256)           // 16 n-tiles GEMM1 (N tile = 256)
#define NT2      (DM / 256)            // 4  n-tiles GEMM2

#define STAGES   4
// per stage: A 16KB + B 32KB (K64 chunk, pure fp16)
#define STAGE_B  49152
#define SMEM_DYN (STAGES * STAGE_B + 64)

// ---------------- static device scratch (fragment-linear tiled) ----------------
__device__ __align__(16) __half g_A1[(size_t)PADSLOTS * DM];
__device__ __align__(16) __half g_B1[(size_t)NE * DFF * DM];
__device__ __align__(16) __half g_H [(size_t)PADSLOTS * DFF];
__device__ __align__(16) __half g_B2[(size_t)NE * DM * DFF];
__device__ __align__(16) float  g_P [(size_t)PADSLOTS * DM];   // gated partials (slot order)

__device__ int   g_tope[NSLOTS];
__device__ float g_topp[NSLOTS];
__device__ int   g_tok_pad[PADSLOTS];
__device__ float g_gw_pad[PADSLOTS];
__device__ int   g_inv[NSLOTS];        // token -> its two slots
__device__ int   g_count[NE];
__device__ int   g_cursor[NE];
__device__ int   g_offpad[NE];
__device__ int   g_mt_e[MT_MAX];
__device__ int   g_mt_valid[MT_MAX];
__device__ int   g_nmt;

struct alignas(16) H8 { __half h[8]; };

// ---------------- PTX helpers ----------------
__device__ __forceinline__ uint32_t smem_u32(const void* p) {
    uint32_t a;
    asm("{ .reg .u64 t; cvta.to.shared.u64 t, %1; cvt.u32.u64 %0, t; }" : "=r"(a) : "l"(p));
    return a;
}
#define MBAR_INIT(a, c) \
    asm volatile("mbarrier.init.shared.b64 [%0], %1;" :: "r"(a), "r"((uint32_t)(c)) : "memory")
#define MBAR_EXPECT_TX(a, b) \
    asm volatile("mbarrier.arrive.expect_tx.shared.b64 _, [%0], %1;" :: "r"(a), "r"((uint32_t)(b)) : "memory")
#define MBAR_ARRIVE(a) \
    asm volatile("mbarrier.arrive.shared.b64 _, [%0];" :: "r"(a) : "memory")

__device__ __forceinline__ void mbar_wait(uint32_t mbar, uint32_t parity) {
    asm volatile(
        "{\n\t.reg .pred P;\n"
        "WL_%=:\n\t"
        "mbarrier.try_wait.parity.acquire.cta.shared::cta.b64 P, [%0], %1, 0x989680;\n\t"
        "@P bra.uni WD_%=;\n\t"
        "bra.uni WL_%=;\n"
        "WD_%=:\n\t}"
        :: "r"(mbar), "r"(parity) : "memory");
}
__device__ __forceinline__ void mbar_wait_relaxed(uint32_t mbar, uint32_t parity) {
    asm volatile(
        "{\n\t.reg .pred P;\n"
        "WL_%=:\n\t"
        "mbarrier.try_wait.parity.relaxed.cta.shared::cta.b64 P, [%0], %1, 0x989680;\n\t"
        "@P bra.uni WD_%=;\n\t"
        "bra.uni WL_%=;\n"
        "WD_%=:\n\t}"
        :: "r"(mbar), "r"(parity) : "memory");
}
__device__ __forceinline__ void bulk_g2s(uint32_t dst, const void* src, uint32_t bytes, uint32_t mbar) {
    asm volatile(
        "cp.async.bulk.shared::cluster.global.mbarrier::complete_tx::bytes [%0], [%1], %2, [%3];"
        :: "r"(dst), "l"(src), "r"(bytes), "r"(mbar) : "memory");
}
__device__ __forceinline__ uint4 lds128(uint32_t a) {
    uint4 v;
    asm volatile("ld.shared.v4.u32 {%0,%1,%2,%3}, [%4];"
                 : "=r"(v.x), "=r"(v.y), "=r"(v.z), "=r"(v.w) : "r"(a));
    return v;
}
__device__ __forceinline__ void mma_f16(float* c, const uint32_t* a, uint32_t b0, uint32_t b1) {
    asm volatile(
        "mma.sync.aligned.m16n8k16.row.col.f32.f16.f16.f32 "
        "{%0,%1,%2,%3}, {%4,%5,%6,%7}, {%8,%9}, {%0,%1,%2,%3};"
        : "+f"(c[0]), "+f"(c[1]), "+f"(c[2]), "+f"(c[3])
        : "r"(a[0]), "r"(a[1]), "r"(a[2]), "r"(a[3]), "r"(b0), "r"(b1));
}
__device__ __forceinline__ uint32_t pack_h2(__half a, __half b) {
    __half2 h = __halves2half2(a, b);
    return *(uint32_t*)&h;
}

// ---------------- kernel 0: routing-state init ----------------
__global__ void init_kernel() {
    const int gid = blockIdx.x * blockDim.x + threadIdx.x;
    if (gid < PADSLOTS) g_tok_pad[gid] = -1;
    if (gid < NE) { g_count[gid] = 0; g_cursor[gid] = 0; }
}

// ---------------- kernel 1: gating (warp per token; R14 access pattern) ----------------
// Lanes read consecutive gw rows (8 sectors per load) and stride-32 scalar x
// (fully coalesced). The R15 "float4" variant put gw at lane-stride 128B and
// became L1-wavefront-bound (measured 83us vs 31.6us for this version).
__global__ void __launch_bounds__(256) gate_kernel(
    const float* __restrict__ x, const float* __restrict__ gw, const float* __restrict__ gb)
{
    const int warp = (blockIdx.x * blockDim.x + threadIdx.x) >> 5;
    const int lane = threadIdx.x & 31;
    if (warp >= TOKENS) return;

    const float* xr = x + (size_t)warp * DM;
    float acc[NE];
#pragma unroll
    for (int e = 0; e < NE; e++) acc[e] = 0.f;
    for (int d = lane; d < DM; d += 32) {
        float xv = xr[d];
        const float4 g0 = *(const float4*)(gw + (size_t)d * NE);
        const float4 g1 = *(const float4*)(gw + (size_t)d * NE + 4);
        acc[0] += xv * g0.x;  acc[1] += xv * g0.y;
        acc[2] += xv * g0.z;  acc[3] += xv * g0.w;
        acc[4] += xv * g1.x;  acc[5] += xv * g1.y;
        acc[6] += xv * g1.z;  acc[7] += xv * g1.w;
    }
#pragma unroll
    for (int e = 0; e < NE; e++) {
#pragma unroll
        for (int off = 16; off; off >>= 1)
            acc[e] += __shfl_xor_sync(0xffffffffu, acc[e], off);
    }
    if (lane == 0) {
        float m = -1e30f;
#pragma unroll
        for (int e = 0; e < NE; e++) { acc[e] += gb[e]; m = fmaxf(m, acc[e]); }
        float s = 0.f;
#pragma unroll
        for (int e = 0; e < NE; e++) { acc[e] = __expf(acc[e] - m); s += acc[e]; }
        const float inv = 1.f / s;
        int i1 = 0; float p1 = acc[0];
#pragma unroll
        for (int e = 1; e < NE; e++) if (acc[e] > p1) { p1 = acc[e]; i1 = e; }
        int i2 = -1; float p2 = -1.f;
#pragma unroll
        for (int e = 0; e < NE; e++) if (e != i1 && acc[e] > p2) { p2 = acc[e]; i2 = e; }
        g_tope[2 * warp + 0] = i1;  g_topp[2 * warp + 0] = p1 * inv;
        g_tope[2 * warp + 1] = i2;  g_topp[2 * warp + 1] = p2 * inv;
        atomicAdd(&g_count[i1], 1);
        atomicAdd(&g_count[i2], 1);
    }
}

// ---------------- kernel 2: scan + padded mtile tables ----------------
__global__ void scan_kernel() {
    int o = 0, m = 0;
    for (int e = 0; e < NE; e++) {
        g_offpad[e] = o;
        const int c = g_count[e];
        const int nt = (c + 127) >> 7;
        for (int t = 0; t < nt; t++) {
            g_mt_e[m] = e;
            g_mt_valid[m] = min(128, c - t * 128);
            m++;
        }
        o += nt * 128;
    }
    g_nmt = m;
}

// ---------------- kernel 3: scatter + inverse map ----------------
__global__ void scatter_kernel() {
    const int t = blockIdx.x * blockDim.x + threadIdx.x;
    if (t >= TOKENS) return;
#pragma unroll
    for (int k = 0; k < 2; k++) {
        const int e = g_tope[2 * t + k];
        const float p = g_topp[2 * t + k];
        const int pos = g_offpad[e] + atomicAdd(&g_cursor[e], 1);
        g_tok_pad[pos] = t;
        g_gw_pad[pos] = p;
        g_inv[2 * t + k] = pos;
    }
}

// ---------------- pregather x -> fragment-linear tiled A1 (fp16) ----------------
__global__ void __launch_bounds__(256) pregather_x(const float* __restrict__ x) {
    const int mt = blockIdx.y;
    if (mt >= g_nmt) return;
    const int kc = blockIdx.x;
    const size_t blk = ((size_t)mt * KCH1 + kc) * 4096;

    for (int f = threadIdx.x; f < 512; f += 256) {
        const int lane = f & 31, w = f >> 5;
        const int ks = w & 1, mi = (w >> 1) & 3, wm = w >> 3;
        const int g = lane >> 2, t = lane & 3;
        const int k0 = kc * 32 + ks * 16 + 2 * t;
        H8 hh;
#pragma unroll
        for (int rr = 0; rr < 2; rr++) {
            const int slot = mt * 128 + wm * 64 + mi * 16 + g + rr * 8;
            const int tok = g_tok_pad[slot];
            float v0 = 0.f, v1 = 0.f, v2 = 0.f, v3 = 0.f;
            if (tok >= 0) {
                const float2 p0 = *(const float2*)(x + (size_t)tok * DM + k0);
                const float2 p1 = *(const float2*)(x + (size_t)tok * DM + k0 + 8);
                v0 = p0.x; v1 = p0.y; v2 = p1.x; v3 = p1.y;
            }
            hh.h[rr * 2 + 0] = __float2half_rn(v0);
            hh.h[rr * 2 + 1] = __float2half_rn(v1);
            hh.h[4 + rr * 2 + 0] = __float2half_rn(v2);
            hh.h[4 + rr * 2 + 1] = __float2half_rn(v3);
        }
        *(uint4*)(g_A1 + blk + (size_t)f * 8) = *(uint4*)&hh;
    }
}

// ---------------- weight tilers: [E][K][N] -> fragment-linear B blocks (N tile 256) ------
template<int N, int NT, int KCH>
__global__ void __launch_bounds__(256) tile_w(
    const float* __restrict__ w, __half* __restrict__ bdst)
{
    const int e = blockIdx.z, nt = blockIdx.y, kc = blockIdx.x;
    const size_t blk = (((size_t)e * NT + nt) * KCH + kc) * 8192;
    const float* we = w + (size_t)e * (size_t)(N) * (NT == NT1 ? DM : DFF);
    const int K_LD = N;

    for (int f = threadIdx.x; f < 1024; f += 256) {
        const int lane = f & 31, wi = f >> 5;
        const int ks = wi & 1, np = (wi >> 1) & 3, wn = wi >> 3;
        const int g = lane >> 2, t = lane & 3;
        const int kb = kc * 32 + ks * 16 + 2 * t;
        H8 hh;
#pragma unroll
        for (int sub = 0; sub < 2; sub++) {
            const int n = nt * 256 + wn * 64 + (2 * np + sub) * 8 + g;
            const int kk[4] = { kb, kb + 1, kb + 8, kb + 9 };
#pragma unroll
            for (int q = 0; q < 4; q++) {
                hh.h[sub * 4 + q] = __float2half_rn(we[(size_t)kk[q] * K_LD + n]);
            }
        }
        *(uint4*)(bdst + blk + (size_t)f * 8) = *(uint4*)&hh;
    }
}

// ---------------- pipelined fragment GEMM: CTA 128x256, warp 64x64, K64 chunks ------
template<int KCH64, int NT, int NDIM, bool IS_G1>
__global__ void __launch_bounds__(256, 1) moe_gemm(
    const __half* __restrict__ A,
    const __half* __restrict__ B,
    const float* __restrict__ bias,
    __half* __restrict__ oH,
    float* __restrict__ oP)
{
    const int mt = blockIdx.x;           // mt fastest -> in-flight CTAs share B (L2 reuse)
    if (mt >= g_nmt) return;
    const int nt = blockIdx.y;
    const int e = g_mt_e[mt];
    const int valid = g_mt_valid[mt];

    extern __shared__ __align__(128) char smem[];
    const uint32_t SB = smem_u32(smem);
    const uint32_t FULLB  = SB + STAGES * STAGE_B;
    const uint32_t EMPTYB = FULLB + 8 * STAGES;

    const int tid = threadIdx.x;
    const int warp = tid >> 5;
    const int lane = tid & 31;

    if (tid == 0) {
#pragma unroll
        for (int s = 0; s < STAGES; s++) {
            MBAR_INIT(FULLB + 8 * s, 1);
            MBAR_INIT(EMPTYB + 8 * s, 8);
        }
    }
    __syncthreads();

    const char* abase = (const char*)A + ((size_t)mt * KCH64) * 16384;
    const char* bbase = (const char*)B + (((size_t)e * NT + nt) * KCH64) * 32768;

    // prologue: fill first 3 stages (prefetch depth 3)
    if (tid == 0) {
#pragma unroll
        for (int c = 0; c < 3 && c < KCH64; c++) {
            const uint32_t sa = SB + c * STAGE_B;
            MBAR_EXPECT_TX(FULLB + 8 * c, STAGE_B);
            bulk_g2s(sa,         abase + (size_t)c * 16384, 16384, FULLB + 8 * c);
            bulk_g2s(sa + 16384, bbase + (size_t)c * 32768, 32768, FULLB + 8 * c);
        }
    }

    const int warpM = warp & 1, warpN = warp >> 1;    // 2 x 4 warp grid, 64x64 tiles
    uint32_t aoff[4][2], boff[4][2];
#pragma unroll
    for (int mi = 0; mi < 4; mi++)
#pragma unroll
        for (int ks = 0; ks < 2; ks++)
            aoff[mi][ks] = (uint32_t)((lane + 32 * (ks + 2 * mi + 8 * warpM)) * 16);
#pragma unroll
    for (int np = 0; np < 4; np++)
#pragma unroll
        for (int ks = 0; ks < 2; ks++)
            boff[np][ks] = (uint32_t)((lane + 32 * (ks + 2 * np + 8 * warpN)) * 16);

    float acc[4][8][4];
#pragma unroll
    for (int i = 0; i < 4; i++)
#pragma unroll
        for (int j = 0; j < 8; j++)
#pragma unroll
            for (int k = 0; k < 4; k++) acc[i][j][k] = 0.f;

    // producer cursor for chunk c+3: first wait on fresh EMPTY uses parity 1
    int pst = 3, pph = 1;
    int cst = 0, cph = 0;

    for (int c = 0; c < KCH64; c++) {
        mbar_wait(FULLB + 8 * cst, cph);

        // early issue: enqueue chunk c+3 loads BEFORE computing chunk c
        if (tid == 0 && c + 3 < KCH64) {
            mbar_wait_relaxed(EMPTYB + 8 * pst, pph);
            const uint32_t da = SB + pst * STAGE_B;
            MBAR_EXPECT_TX(FULLB + 8 * pst, STAGE_B);
            bulk_g2s(da,         abase + (size_t)(c + 3) * 16384, 16384, FULLB + 8 * pst);
            bulk_g2s(da + 16384, bbase + (size_t)(c + 3) * 32768, 32768, FULLB + 8 * pst);
            if (++pst == STAGES) { pst = 0; pph ^= 1; }
        }

        const uint32_t sa = SB + cst * STAGE_B;
#pragma unroll
        for (int sub = 0; sub < 2; sub++) {       // two K32 blocks per chunk
            const uint32_t saA = sa + sub * 8192;
            const uint32_t saB = sa + 16384 + sub * 16384;
#pragma unroll
            for (int ks = 0; ks < 2; ks++) {
                uint4 bh[4];
#pragma unroll
                for (int np = 0; np < 4; np++)
                    bh[np] = lds128(saB + boff[np][ks]);
#pragma unroll
                for (int mi = 0; mi < 4; mi++) {
                    const uint4 ah = lds128(saA + aoff[mi][ks]);
#pragma unroll
                    for (int np = 0; np < 4; np++) {
                        mma_f16(acc[mi][2 * np],     (const uint32_t*)&ah, bh[np].x, bh[np].y);
                        mma_f16(acc[mi][2 * np + 1], (const uint32_t*)&ah, bh[np].z, bh[np].w);
                    }
                }
            }
        }
        __syncwarp();
        if (lane == 0) MBAR_ARRIVE(EMPTYB + 8 * cst);
        if (++cst == STAGES) { cst = 0; cph ^= 1; }
    }

    // ---------------- epilogue ----------------
    const int g = lane >> 2, t = lane & 3;
    if (IS_G1) {
        // Write H in G2's A-fragment-linear layout (bias + SiLU, fp16).
#pragma unroll
        for (int n8 = 0; n8 < 8; n8++) {
            const int col = nt * 256 + warpN * 64 + n8 * 8 + 2 * t;
            const float b0 = bias[(size_t)e * NDIM + col];
            const float b1 = bias[(size_t)e * NDIM + col + 1];
            const int kcH = nt * 8 + warpN * 2 + (n8 >> 2);
            const int ks2 = (n8 >> 1) & 1;
#pragma unroll
            for (int mi = 0; mi < 4; mi++) {
                const int r0 = warpM * 64 + mi * 16 + g;
                float v0 = acc[mi][n8][0] + b0, v1 = acc[mi][n8][1] + b1;
                float v2 = acc[mi][n8][2] + b0, v3 = acc[mi][n8][3] + b1;
                v0 = v0 / (1.f + __expf(-v0));
                v1 = v1 / (1.f + __expf(-v1));
                v2 = v2 / (1.f + __expf(-v2));
                v3 = v3 / (1.f + __expf(-v3));
                if (r0 >= valid)     { v0 = 0.f; v1 = 0.f; }
                if (r0 + 8 >= valid) { v2 = 0.f; v3 = 0.f; }
                const __half h0 = __float2half_rn(v0), h1 = __float2half_rn(v1);
                const __half h2 = __float2half_rn(v2), h3 = __float2half_rn(v3);
                const int fA = lane + 32 * (ks2 + 2 * mi + 8 * warpM);
                const size_t off = ((size_t)mt * (DFF / 32) + kcH) * 4096 +
                                   (size_t)fA * 8 + (size_t)(n8 & 1) * 4;
                uint2 sh;
                sh.x = pack_h2(h0, h1);  sh.y = pack_h2(h2, h3);
                *(uint2*)(oH + off) = sh;
            }
        }
    } else {
        // gated coalesced partial stores (slot order); combined later per token
#pragma unroll
        for (int mi = 0; mi < 4; mi++) {
            const int r0 = warpM * 64 + mi * 16 + g;
            const int slot0 = mt * 128 + r0;
            const int slot1 = slot0 + 8;
            const bool ok0 = r0 < valid;
            const bool ok1 = (r0 + 8) < valid;
            const float gw0 = ok0 ? g_gw_pad[slot0] : 0.f;
            const float gw1 = ok1 ? g_gw_pad[slot1] : 0.f;
#pragma unroll
            for (int n8 = 0; n8 < 8; n8++) {
                const int col = nt * 256 + warpN * 64 + n8 * 8 + 2 * t;
                const float b0 = bias[(size_t)e * NDIM + col];
                const float b1 = bias[(size_t)e * NDIM + col + 1];
                if (ok0) {
                    float2 v = make_float2(gw0 * (acc[mi][n8][0] + b0),
                                           gw0 * (acc[mi][n8][1] + b1));
                    *(float2*)(oP + (size_t)slot0 * DM + col) = v;
                }
                if (ok1) {
                    float2 v = make_float2(gw1 * (acc[mi][n8][2] + b0),
                                           gw1 * (acc[mi][n8][3] + b1));
                    *(float2*)(oP + (size_t)slot1 * DM + col) = v;
                }
            }
        }
    }
}

// ---------------- combine: out[t] = P[slot0(t)] + P[slot1(t)] ----------------
__global__ void __launch_bounds__(256) combine_kernel(float4* __restrict__ out) {
    const int t = blockIdx.x;
    const int d = threadIdx.x;            // DM/4 = 256 float4 per token
    const int s0 = g_inv[2 * t + 0];
    const int s1 = g_inv[2 * t + 1];
    const float4 a = *(const float4*)(g_P + (size_t)s0 * DM + d * 4);
    const float4 b = *(const float4*)(g_P + (size_t)s1 * DM + d * 4);
    out[(size_t)t * (DM / 4) + d] = make_float4(a.x + b.x, a.y + b.y, a.z + b.z, a.w + b.w);
}

// ---------------- launch ----------------
extern "C" void kernel_launch(void* const* d_in, const int* in_sizes, int n_in,
                              void* d_out, int out_size)
{
    const float* x      = (const float*)d_in[0];
    const float* gate_w = (const float*)d_in[1];
    const float* gate_b = (const float*)d_in[2];
    const float* w1     = (const float*)d_in[3];
    const float* b1     = (const float*)d_in[4];
    const float* w2     = (const float*)d_in[5];
    const float* b2     = (const float*)d_in[6];
    float* out = (float*)d_out;

    cudaFuncSetAttribute(moe_gemm<KC64_1, NT1, DFF, true>,
                         cudaFuncAttributeMaxDynamicSharedMemorySize, SMEM_DYN);
    cudaFuncSetAttribute(moe_gemm<KC64_2, NT2, DM, false>,
                         cudaFuncAttributeMaxDynamicSharedMemorySize, SMEM_DYN);

    __half *a1, *b1t, *h, *b2t;
    float *pbuf;
    cudaGetSymbolAddress((void**)&a1,   g_A1);
    cudaGetSymbolAddress((void**)&b1t,  g_B1);
    cudaGetSymbolAddress((void**)&h,    g_H);
    cudaGetSymbolAddress((void**)&b2t,  g_B2);
    cudaGetSymbolAddress((void**)&pbuf, g_P);

    // forked capture branch for weight tiling (independent of x-routing chain).
    // Handles created per call and deliberately not destroyed (few calls total;
    // destroying a stream mid-capture is hazardous). No device memory allocated.
    cudaStream_t s1;
    cudaEvent_t evRoot, evW1, evW2;
    cudaStreamCreateWithFlags(&s1, cudaStreamNonBlocking);
    cudaEventCreateWithFlags(&evRoot, cudaEventDisableTiming);
    cudaEventCreateWithFlags(&evW1, cudaEventDisableTiming);
    cudaEventCreateWithFlags(&evW2, cudaEventDisableTiming);

    cudaEventRecord(evRoot, 0);
    cudaStreamWaitEvent(s1, evRoot, 0);

    // branch s1: weight tiling
    tile_w<DFF, NT1, KCH1><<<dim3(KCH1, NT1, NE), 256, 0, s1>>>(w1, b1t);
    cudaEventRecord(evW1, s1);
    tile_w<DM,  NT2, KCH2><<<dim3(KCH2, NT2, NE), 256, 0, s1>>>(w2, b2t);
    cudaEventRecord(evW2, s1);

    // main branch: routing + x prep
    init_kernel<<<PADSLOTS / 256, 256>>>();
    gate_kernel<<<TOKENS / 8, 256>>>(x, gate_w, gate_b);
    scan_kernel<<<1, 1>>>();
    scatter_kernel<<<TOKENS / 256, 256>>>();
    pregather_x<<<dim3(KCH1, MT_MAX), 256>>>(x);

    cudaStreamWaitEvent(0, evW1, 0);
    moe_gemm<KC64_1, NT1, DFF, true><<<dim3(MT_MAX, NT1), 256, SMEM_DYN>>>(
        a1, b1t, b1, h, nullptr);

    cudaStreamWaitEvent(0, evW2, 0);
    moe_gemm<KC64_2, NT2, DM, false><<<dim3(MT_MAX, NT2), 256, SMEM_DYN>>>(
        h, b2t, b2, nullptr, pbuf);

    combine_kernel<<<TOKENS, 256>>>((float4*)out);
}

// round 17
// speedup vs baseline: 1.0368x; 1.0002x over previous
#include <cuda_runtime.h>
#include <cuda_fp16.h>
#include <cstdint>
#include <math.h>

#define TOKENS   8192
#define DM       1024
#define DFF      4096
#define NE       8
#define NSLOTS   (TOKENS * 2)

#define MT_MAX   (NSLOTS / 128 + NE)   // 136 padded m-tiles max
#define PADSLOTS (MT_MAX * 128)        // 17408
#define KCH1     (DM / 32)             // 32 K32 blocks (layout unit)
#define KCH2     (DFF / 32)            // 128 K32 blocks
#define KC64_1   (DM / 64)             // 16 mainloop chunks GEMM1
#define KC64_2   (DFF / 64)            // 64 mainloop chunks GEMM2
#define NT1      (DFF / 256)           // 16 n-tiles GEMM1 (N tile = 256)
#define NT2      (DM / 256)            // 4  n-tiles GEMM2

#define STAGES   4
// per stage: A 16KB + B 32KB (K64 chunk, pure fp16)
#define STAGE_B  49152
#define SMEM_DYN (STAGES * STAGE_B + 64)

// ---------------- static device scratch (fragment-linear tiled) ----------------
__device__ __align__(16) __half g_A1[(size_t)PADSLOTS * DM];
__device__ __align__(16) __half g_B1[(size_t)NE * DFF * DM];
__device__ __align__(16) __half g_H [(size_t)PADSLOTS * DFF];
__device__ __align__(16) __half g_B2[(size_t)NE * DM * DFF];
__device__ __align__(16) float  g_P [(size_t)PADSLOTS * DM];   // gated partials (slot order)

__device__ int   g_tope[NSLOTS];
__device__ float g_topp[NSLOTS];
__device__ int   g_tok_pad[PADSLOTS];
__device__ float g_gw_pad[PADSLOTS];
__device__ int   g_inv[NSLOTS];        // token -> its two slots
__device__ int   g_count[NE];
__device__ int   g_cursor[NE];
__device__ int   g_offpad[NE];
__device__ int   g_mt_e[MT_MAX];
__device__ int   g_mt_valid[MT_MAX];
__device__ int   g_nmt;

struct alignas(16) H8 { __half h[8]; };

// ---------------- PTX helpers ----------------
__device__ __forceinline__ uint32_t smem_u32(const void* p) {
    uint32_t a;
    asm("{ .reg .u64 t; cvta.to.shared.u64 t, %1; cvt.u32.u64 %0, t; }" : "=r"(a) : "l"(p));
    return a;
}
#define MBAR_INIT(a, c) \
    asm volatile("mbarrier.init.shared.b64 [%0], %1;" :: "r"(a), "r"((uint32_t)(c)) : "memory")
#define MBAR_EXPECT_TX(a, b) \
    asm volatile("mbarrier.arrive.expect_tx.shared.b64 _, [%0], %1;" :: "r"(a), "r"((uint32_t)(b)) : "memory")
#define MBAR_ARRIVE(a) \
    asm volatile("mbarrier.arrive.shared.b64 _, [%0];" :: "r"(a) : "memory")

__device__ __forceinline__ void mbar_wait(uint32_t mbar, uint32_t parity) {
    asm volatile(
        "{\n\t.reg .pred P;\n"
        "WL_%=:\n\t"
        "mbarrier.try_wait.parity.acquire.cta.shared::cta.b64 P, [%0], %1, 0x989680;\n\t"
        "@P bra.uni WD_%=;\n\t"
        "bra.uni WL_%=;\n"
        "WD_%=:\n\t}"
        :: "r"(mbar), "r"(parity) : "memory");
}
__device__ __forceinline__ void mbar_wait_relaxed(uint32_t mbar, uint32_t parity) {
    asm volatile(
        "{\n\t.reg .pred P;\n"
        "WL_%=:\n\t"
        "mbarrier.try_wait.parity.relaxed.cta.shared::cta.b64 P, [%0], %1, 0x989680;\n\t"
        "@P bra.uni WD_%=;\n\t"
        "bra.uni WL_%=;\n"
        "WD_%=:\n\t}"
        :: "r"(mbar), "r"(parity) : "memory");
}
__device__ __forceinline__ void bulk_g2s(uint32_t dst, const void* src, uint32_t bytes, uint32_t mbar) {
    asm volatile(
        "cp.async.bulk.shared::cluster.global.mbarrier::complete_tx::bytes [%0], [%1], %2, [%3];"
        :: "r"(dst), "l"(src), "r"(bytes), "r"(mbar) : "memory");
}
__device__ __forceinline__ uint4 lds128(uint32_t a) {
    uint4 v;
    asm volatile("ld.shared.v4.u32 {%0,%1,%2,%3}, [%4];"
                 : "=r"(v.x), "=r"(v.y), "=r"(v.z), "=r"(v.w) : "r"(a));
    return v;
}
__device__ __forceinline__ void mma_f16(float* c, const uint32_t* a, uint32_t b0, uint32_t b1) {
    asm volatile(
        "mma.sync.aligned.m16n8k16.row.col.f32.f16.f16.f32 "
        "{%0,%1,%2,%3}, {%4,%5,%6,%7}, {%8,%9}, {%0,%1,%2,%3};"
        : "+f"(c[0]), "+f"(c[1]), "+f"(c[2]), "+f"(c[3])
        : "r"(a[0]), "r"(a[1]), "r"(a[2]), "r"(a[3]), "r"(b0), "r"(b1));
}
__device__ __forceinline__ uint32_t pack_h2(__half a, __half b) {
    __half2 h = __halves2half2(a, b);
    return *(uint32_t*)&h;
}

// ---------------- kernel 0: routing-state init ----------------
__global__ void init_kernel() {
    const int gid = blockIdx.x * blockDim.x + threadIdx.x;
    if (gid < PADSLOTS) g_tok_pad[gid] = -1;
    if (gid < NE) { g_count[gid] = 0; g_cursor[gid] = 0; }
}

// ---------------- kernel 1: gating (warp per token; 4-way ILP, R14 gw pattern) ---------
// Lanes still read CONSECUTIVE gw rows (8 sectors/load, the proven-good pattern);
// each lane now runs 4 independent d-chains (d, d+256, d+512, d+768) to raise
// the DRAM-stream MLP from ~1 to ~4 (gate was measured latency-bound: 33us,
// DRAM 12%, issue 23%).
__global__ void __launch_bounds__(256) gate_kernel(
    const float* __restrict__ x, const float* __restrict__ gw, const float* __restrict__ gb)
{
    const int warp = (blockIdx.x * blockDim.x + threadIdx.x) >> 5;
    const int lane = threadIdx.x & 31;
    if (warp >= TOKENS) return;

    const float* xr = x + (size_t)warp * DM;
    float acc[NE];
#pragma unroll
    for (int e = 0; e < NE; e++) acc[e] = 0.f;

#pragma unroll
    for (int it = 0; it < 8; it++) {
        const int d0 = it * 32 + lane;
        float xv[4];
        xv[0] = xr[d0];
        xv[1] = xr[d0 + 256];
        xv[2] = xr[d0 + 512];
        xv[3] = xr[d0 + 768];
#pragma unroll
        for (int q = 0; q < 4; q++) {
            const int d = d0 + q * 256;
            const float4 g0 = *(const float4*)(gw + (size_t)d * NE);
            const float4 g1 = *(const float4*)(gw + (size_t)d * NE + 4);
            acc[0] += xv[q] * g0.x;  acc[1] += xv[q] * g0.y;
            acc[2] += xv[q] * g0.z;  acc[3] += xv[q] * g0.w;
            acc[4] += xv[q] * g1.x;  acc[5] += xv[q] * g1.y;
            acc[6] += xv[q] * g1.z;  acc[7] += xv[q] * g1.w;
        }
    }
#pragma unroll
    for (int e = 0; e < NE; e++) {
#pragma unroll
        for (int off = 16; off; off >>= 1)
            acc[e] += __shfl_xor_sync(0xffffffffu, acc[e], off);
    }
    if (lane == 0) {
        float m = -1e30f;
#pragma unroll
        for (int e = 0; e < NE; e++) { acc[e] += gb[e]; m = fmaxf(m, acc[e]); }
        float s = 0.f;
#pragma unroll
        for (int e = 0; e < NE; e++) { acc[e] = __expf(acc[e] - m); s += acc[e]; }
        const float inv = 1.f / s;
        int i1 = 0; float p1 = acc[0];
#pragma unroll
        for (int e = 1; e < NE; e++) if (acc[e] > p1) { p1 = acc[e]; i1 = e; }
        int i2 = -1; float p2 = -1.f;
#pragma unroll
        for (int e = 0; e < NE; e++) if (e != i1 && acc[e] > p2) { p2 = acc[e]; i2 = e; }
        g_tope[2 * warp + 0] = i1;  g_topp[2 * warp + 0] = p1 * inv;
        g_tope[2 * warp + 1] = i2;  g_topp[2 * warp + 1] = p2 * inv;
        atomicAdd(&g_count[i1], 1);
        atomicAdd(&g_count[i2], 1);
    }
}

// ---------------- kernel 2: scan + padded mtile tables ----------------
__global__ void scan_kernel() {
    int o = 0, m = 0;
    for (int e = 0; e < NE; e++) {
        g_offpad[e] = o;
        const int c = g_count[e];
        const int nt = (c + 127) >> 7;
        for (int t = 0; t < nt; t++) {
            g_mt_e[m] = e;
            g_mt_valid[m] = min(128, c - t * 128);
            m++;
        }
        o += nt * 128;
    }
    g_nmt = m;
}

// ---------------- kernel 3: scatter + inverse map ----------------
__global__ void scatter_kernel() {
    const int t = blockIdx.x * blockDim.x + threadIdx.x;
    if (t >= TOKENS) return;
#pragma unroll
    for (int k = 0; k < 2; k++) {
        const int e = g_tope[2 * t + k];
        const float p = g_topp[2 * t + k];
        const int pos = g_offpad[e] + atomicAdd(&g_cursor[e], 1);
        g_tok_pad[pos] = t;
        g_gw_pad[pos] = p;
        g_inv[2 * t + k] = pos;
    }
}

// ---------------- pregather x -> fragment-linear tiled A1 (fp16) ----------------
__global__ void __launch_bounds__(256) pregather_x(const float* __restrict__ x) {
    const int mt = blockIdx.y;
    if (mt >= g_nmt) return;
    const int kc = blockIdx.x;
    const size_t blk = ((size_t)mt * KCH1 + kc) * 4096;

    for (int f = threadIdx.x; f < 512; f += 256) {
        const int lane = f & 31, w = f >> 5;
        const int ks = w & 1, mi = (w >> 1) & 3, wm = w >> 3;
        const int g = lane >> 2, t = lane & 3;
        const int k0 = kc * 32 + ks * 16 + 2 * t;
        H8 hh;
#pragma unroll
        for (int rr = 0; rr < 2; rr++) {
            const int slot = mt * 128 + wm * 64 + mi * 16 + g + rr * 8;
            const int tok = g_tok_pad[slot];
            float v0 = 0.f, v1 = 0.f, v2 = 0.f, v3 = 0.f;
            if (tok >= 0) {
                const float2 p0 = *(const float2*)(x + (size_t)tok * DM + k0);
                const float2 p1 = *(const float2*)(x + (size_t)tok * DM + k0 + 8);
                v0 = p0.x; v1 = p0.y; v2 = p1.x; v3 = p1.y;
            }
            hh.h[rr * 2 + 0] = __float2half_rn(v0);
            hh.h[rr * 2 + 1] = __float2half_rn(v1);
            hh.h[4 + rr * 2 + 0] = __float2half_rn(v2);
            hh.h[4 + rr * 2 + 1] = __float2half_rn(v3);
        }
        *(uint4*)(g_A1 + blk + (size_t)f * 8) = *(uint4*)&hh;
    }
}

// ---------------- weight tilers: [E][K][N] -> fragment-linear B blocks (N tile 256) ------
template<int N, int NT, int KCH>
__global__ void __launch_bounds__(256) tile_w(
    const float* __restrict__ w, __half* __restrict__ bdst)
{
    const int e = blockIdx.z, nt = blockIdx.y, kc = blockIdx.x;
    const size_t blk = (((size_t)e * NT + nt) * KCH + kc) * 8192;
    const float* we = w + (size_t)e * (size_t)(N) * (NT == NT1 ? DM : DFF);
    const int K_LD = N;

    for (int f = threadIdx.x; f < 1024; f += 256) {
        const int lane = f & 31, wi = f >> 5;
        const int ks = wi & 1, np = (wi >> 1) & 3, wn = wi >> 3;
        const int g = lane >> 2, t = lane & 3;
        const int kb = kc * 32 + ks * 16 + 2 * t;
        H8 hh;
#pragma unroll
        for (int sub = 0; sub < 2; sub++) {
            const int n = nt * 256 + wn * 64 + (2 * np + sub) * 8 + g;
            const int kk[4] = { kb, kb + 1, kb + 8, kb + 9 };
#pragma unroll
            for (int q = 0; q < 4; q++) {
                hh.h[sub * 4 + q] = __float2half_rn(we[(size_t)kk[q] * K_LD + n]);
            }
        }
        *(uint4*)(bdst + blk + (size_t)f * 8) = *(uint4*)&hh;
    }
}

// ---------------- pipelined fragment GEMM: CTA 128x256, warp 64x64, K64 chunks ------
template<int KCH64, int NT, int NDIM, bool IS_G1>
__global__ void __launch_bounds__(256, 1) moe_gemm(
    const __half* __restrict__ A,
    const __half* __restrict__ B,
    const float* __restrict__ bias,
    __half* __restrict__ oH,
    float* __restrict__ oP)
{
    const int mt = blockIdx.x;           // mt fastest -> in-flight CTAs share B (L2 reuse)
    if (mt >= g_nmt) return;
    const int nt = blockIdx.y;
    const int e = g_mt_e[mt];
    const int valid = g_mt_valid[mt];

    extern __shared__ __align__(128) char smem[];
    const uint32_t SB = smem_u32(smem);
    const uint32_t FULLB  = SB + STAGES * STAGE_B;
    const uint32_t EMPTYB = FULLB + 8 * STAGES;

    const int tid = threadIdx.x;
    const int warp = tid >> 5;
    const int lane = tid & 31;

    if (tid == 0) {
#pragma unroll
        for (int s = 0; s < STAGES; s++) {
            MBAR_INIT(FULLB + 8 * s, 1);
            MBAR_INIT(EMPTYB + 8 * s, 8);
        }
    }
    __syncthreads();

    const char* abase = (const char*)A + ((size_t)mt * KCH64) * 16384;
    const char* bbase = (const char*)B + (((size_t)e * NT + nt) * KCH64) * 32768;

    // prologue: fill first 3 stages (prefetch depth 3)
    if (tid == 0) {
#pragma unroll
        for (int c = 0; c < 3 && c < KCH64; c++) {
            const uint32_t sa = SB + c * STAGE_B;
            MBAR_EXPECT_TX(FULLB + 8 * c, STAGE_B);
            bulk_g2s(sa,         abase + (size_t)c * 16384, 16384, FULLB + 8 * c);
            bulk_g2s(sa + 16384, bbase + (size_t)c * 32768, 32768, FULLB + 8 * c);
        }
    }

    const int warpM = warp & 1, warpN = warp >> 1;    // 2 x 4 warp grid, 64x64 tiles
    uint32_t aoff[4][2], boff[4][2];
#pragma unroll
    for (int mi = 0; mi < 4; mi++)
#pragma unroll
        for (int ks = 0; ks < 2; ks++)
            aoff[mi][ks] = (uint32_t)((lane + 32 * (ks + 2 * mi + 8 * warpM)) * 16);
#pragma unroll
    for (int np = 0; np < 4; np++)
#pragma unroll
        for (int ks = 0; ks < 2; ks++)
            boff[np][ks] = (uint32_t)((lane + 32 * (ks + 2 * np + 8 * warpN)) * 16);

    float acc[4][8][4];
#pragma unroll
    for (int i = 0; i < 4; i++)
#pragma unroll
        for (int j = 0; j < 8; j++)
#pragma unroll
            for (int k = 0; k < 4; k++) acc[i][j][k] = 0.f;

    // producer cursor for chunk c+3: first wait on fresh EMPTY uses parity 1
    int pst = 3, pph = 1;
    int cst = 0, cph = 0;

    for (int c = 0; c < KCH64; c++) {
        mbar_wait(FULLB + 8 * cst, cph);

        // early issue: enqueue chunk c+3 loads BEFORE computing chunk c
        if (tid == 0 && c + 3 < KCH64) {
            mbar_wait_relaxed(EMPTYB + 8 * pst, pph);
            const uint32_t da = SB + pst * STAGE_B;
            MBAR_EXPECT_TX(FULLB + 8 * pst, STAGE_B);
            bulk_g2s(da,         abase + (size_t)(c + 3) * 16384, 16384, FULLB + 8 * pst);
            bulk_g2s(da + 16384, bbase + (size_t)(c + 3) * 32768, 32768, FULLB + 8 * pst);
            if (++pst == STAGES) { pst = 0; pph ^= 1; }
        }

        const uint32_t sa = SB + cst * STAGE_B;
#pragma unroll
        for (int sub = 0; sub < 2; sub++) {       // two K32 blocks per chunk
            const uint32_t saA = sa + sub * 8192;
            const uint32_t saB = sa + 16384 + sub * 16384;
#pragma unroll
            for (int ks = 0; ks < 2; ks++) {
                uint4 bh[4];
#pragma unroll
                for (int np = 0; np < 4; np++)
                    bh[np] = lds128(saB + boff[np][ks]);
#pragma unroll
                for (int mi = 0; mi < 4; mi++) {
                    const uint4 ah = lds128(saA + aoff[mi][ks]);
#pragma unroll
                    for (int np = 0; np < 4; np++) {
                        mma_f16(acc[mi][2 * np],     (const uint32_t*)&ah, bh[np].x, bh[np].y);
                        mma_f16(acc[mi][2 * np + 1], (const uint32_t*)&ah, bh[np].z, bh[np].w);
                    }
                }
            }
        }
        __syncwarp();
        if (lane == 0) MBAR_ARRIVE(EMPTYB + 8 * cst);
        if (++cst == STAGES) { cst = 0; cph ^= 1; }
    }

    // ---------------- epilogue ----------------
    const int g = lane >> 2, t = lane & 3;
    if (IS_G1) {
        // Write H in G2's A-fragment-linear layout (bias + SiLU, fp16).
#pragma unroll
        for (int n8 = 0; n8 < 8; n8++) {
            const int col = nt * 256 + warpN * 64 + n8 * 8 + 2 * t;
            const float b0 = bias[(size_t)e * NDIM + col];
            const float b1 = bias[(size_t)e * NDIM + col + 1];
            const int kcH = nt * 8 + warpN * 2 + (n8 >> 2);
            const int ks2 = (n8 >> 1) & 1;
#pragma unroll
            for (int mi = 0; mi < 4; mi++) {
                const int r0 = warpM * 64 + mi * 16 + g;
                float v0 = acc[mi][n8][0] + b0, v1 = acc[mi][n8][1] + b1;
                float v2 = acc[mi][n8][2] + b0, v3 = acc[mi][n8][3] + b1;
                v0 = v0 / (1.f + __expf(-v0));
                v1 = v1 / (1.f + __expf(-v1));
                v2 = v2 / (1.f + __expf(-v2));
                v3 = v3 / (1.f + __expf(-v3));
                if (r0 >= valid)     { v0 = 0.f; v1 = 0.f; }
                if (r0 + 8 >= valid) { v2 = 0.f; v3 = 0.f; }
                const __half h0 = __float2half_rn(v0), h1 = __float2half_rn(v1);
                const __half h2 = __float2half_rn(v2), h3 = __float2half_rn(v3);
                const int fA = lane + 32 * (ks2 + 2 * mi + 8 * warpM);
                const size_t off = ((size_t)mt * (DFF / 32) + kcH) * 4096 +
                                   (size_t)fA * 8 + (size_t)(n8 & 1) * 4;
                uint2 sh;
                sh.x = pack_h2(h0, h1);  sh.y = pack_h2(h2, h3);
                *(uint2*)(oH + off) = sh;
            }
        }
    } else {
        // gated coalesced partial stores (slot order); combined later per token
#pragma unroll
        for (int mi = 0; mi < 4; mi++) {
            const int r0 = warpM * 64 + mi * 16 + g;
            const int slot0 = mt * 128 + r0;
            const int slot1 = slot0 + 8;
            const bool ok0 = r0 < valid;
            const bool ok1 = (r0 + 8) < valid;
            const float gw0 = ok0 ? g_gw_pad[slot0] : 0.f;
            const float gw1 = ok1 ? g_gw_pad[slot1] : 0.f;
#pragma unroll
            for (int n8 = 0; n8 < 8; n8++) {
                const int col = nt * 256 + warpN * 64 + n8 * 8 + 2 * t;
                const float b0 = bias[(size_t)e * NDIM + col];
                const float b1 = bias[(size_t)e * NDIM + col + 1];
                if (ok0) {
                    float2 v = make_float2(gw0 * (acc[mi][n8][0] + b0),
                                           gw0 * (acc[mi][n8][1] + b1));
                    *(float2*)(oP + (size_t)slot0 * DM + col) = v;
                }
                if (ok1) {
                    float2 v = make_float2(gw1 * (acc[mi][n8][2] + b0),
                                           gw1 * (acc[mi][n8][3] + b1));
                    *(float2*)(oP + (size_t)slot1 * DM + col) = v;
                }
            }
        }
    }
}

// ---------------- combine: out[t] = P[slot0(t)] + P[slot1(t)] ----------------
__global__ void __launch_bounds__(256) combine_kernel(float4* __restrict__ out) {
    const int t = blockIdx.x;
    const int d = threadIdx.x;            // DM/4 = 256 float4 per token
    const int s0 = g_inv[2 * t + 0];
    const int s1 = g_inv[2 * t + 1];
    const float4 a = *(const float4*)(g_P + (size_t)s0 * DM + d * 4);
    const float4 b = *(const float4*)(g_P + (size_t)s1 * DM + d * 4);
    out[(size_t)t * (DM / 4) + d] = make_float4(a.x + b.x, a.y + b.y, a.z + b.z, a.w + b.w);
}

// ---------------- launch ----------------
extern "C" void kernel_launch(void* const* d_in, const int* in_sizes, int n_in,
                              void* d_out, int out_size)
{
    const float* x      = (const float*)d_in[0];
    const float* gate_w = (const float*)d_in[1];
    const float* gate_b = (const float*)d_in[2];
    const float* w1     = (const float*)d_in[3];
    const float* b1     = (const float*)d_in[4];
    const float* w2     = (const float*)d_in[5];
    const float* b2     = (const float*)d_in[6];
    float* out = (float*)d_out;

    cudaFuncSetAttribute(moe_gemm<KC64_1, NT1, DFF, true>,
                         cudaFuncAttributeMaxDynamicSharedMemorySize, SMEM_DYN);
    cudaFuncSetAttribute(moe_gemm<KC64_2, NT2, DM, false>,
                         cudaFuncAttributeMaxDynamicSharedMemorySize, SMEM_DYN);

    __half *a1, *b1t, *h, *b2t;
    float *pbuf;
    cudaGetSymbolAddress((void**)&a1,   g_A1);
    cudaGetSymbolAddress((void**)&b1t,  g_B1);
    cudaGetSymbolAddress((void**)&h,    g_H);
    cudaGetSymbolAddress((void**)&b2t,  g_B2);
    cudaGetSymbolAddress((void**)&pbuf, g_P);

    // forked capture branch for weight tiling (independent of x-routing chain).
    // Handles created per call and deliberately not destroyed (few calls total;
    // destroying a stream mid-capture is hazardous). No device memory allocated.
    cudaStream_t s1;
    cudaEvent_t evRoot, evW1, evW2;
    cudaStreamCreateWithFlags(&s1, cudaStreamNonBlocking);
    cudaEventCreateWithFlags(&evRoot, cudaEventDisableTiming);
    cudaEventCreateWithFlags(&evW1, cudaEventDisableTiming);
    cudaEventCreateWithFlags(&evW2, cudaEventDisableTiming);

    cudaEventRecord(evRoot, 0);
    cudaStreamWaitEvent(s1, evRoot, 0);

    // branch s1: weight tiling
    tile_w<DFF, NT1, KCH1><<<dim3(KCH1, NT1, NE), 256, 0, s1>>>(w1, b1t);
    cudaEventRecord(evW1, s1);
    tile_w<DM,  NT2, KCH2><<<dim3(KCH2, NT2, NE), 256, 0, s1>>>(w2, b2t);
    cudaEventRecord(evW2, s1);

    // main branch: routing + x prep
    init_kernel<<<PADSLOTS / 256, 256>>>();
    gate_kernel<<<TOKENS / 8, 256>>>(x, gate_w, gate_b);
    scan_kernel<<<1, 1>>>();
    scatter_kernel<<<TOKENS / 256, 256>>>();
    pregather_x<<<dim3(KCH1, MT_MAX), 256>>>(x);

    cudaStreamWaitEvent(0, evW1, 0);
    moe_gemm<KC64_1, NT1, DFF, true><<<dim3(MT_MAX, NT1), 256, SMEM_DYN>>>(
        a1, b1t, b1, h, nullptr);

    cudaStreamWaitEvent(0, evW2, 0);
    moe_gemm<KC64_2, NT2, DM, false><<<dim3(MT_MAX, NT2), 256, SMEM_DYN>>>(
        h, b2t, b2, nullptr, pbuf);

    combine_kernel<<<TOKENS, 256>>>((float4*)out);
}